// round 1
// baseline (speedup 1.0000x reference)
#include <cuda_runtime.h>

#define IN_F   128
#define HID_F  128
#define OUT_F  64
#define MAX_N  100000

// ---------------- scratch (static device memory; no allocations) ----------------
__device__ float g_deg [MAX_N];
__device__ float g_dinv[MAX_N];
__device__ float g_h0  [(size_t)MAX_N * HID_F];   // x @ W1
__device__ float g_agg1[(size_t)MAX_N * HID_F];   // layer-1 aggregation (pre-relu)
__device__ float g_h2  [(size_t)MAX_N * OUT_F];   // relu(agg1) @ W2
__device__ int   g_is64;

// ---------------- edge-index dtype detection (int32 vs int64) -------------------
// Values are node ids < 100000, so for int64 little-endian storage every odd
// 32-bit word of the buffer is zero. For int32 the odd words are random ids
// (zero w.p. 1e-5 each) -> 32 probes make misdetection ~impossible.
__global__ void detect_idx_dtype(const unsigned int* __restrict__ w) {
    if (threadIdx.x == 0 && blockIdx.x == 0) {
        int is64 = 1;
        for (int i = 1; i < 64; i += 2)
            if (w[i] != 0u) is64 = 0;
        g_is64 = is64;
    }
}

__global__ void zero_deg(int n) {
    int i = blockIdx.x * blockDim.x + threadIdx.x;
    if (i < n) g_deg[i] = 0.f;
}

__global__ void deg_kernel(const void* __restrict__ ei, int E) {
    const int is64 = g_is64;
    int i = blockIdx.x * blockDim.x + threadIdx.x;
    if (i < E) {
        long long d = is64 ? ((const long long*)ei)[(size_t)E + i]
                           : (long long)((const int*)ei)[(size_t)E + i];
        atomicAdd(&g_deg[d], 1.0f);
    }
}

__global__ void dinv_kernel(int n) {
    int i = blockIdx.x * blockDim.x + threadIdx.x;
    if (i < n) g_dinv[i] = rsqrtf(g_deg[i] + 1.0f);
}

// ---------------- GEMM: C[M,NC] = op(A)[M,K] @ W[K,NC] (+bias) -------------------
// W cached whole in dynamic SMEM. One row per warp; lane owns NC/32 columns.
template<int K, int NC, bool RELU_IN, bool BIAS>
__global__ void gemm_kernel(const float* __restrict__ A, const float* __restrict__ W,
                            const float* __restrict__ bias, float* __restrict__ C, int M) {
    extern __shared__ float Wsh[];            // K*NC floats
    __shared__ float xs[8][K];

    const int tid = threadIdx.x;
    for (int i = tid; i < K * NC / 4; i += blockDim.x)
        ((float4*)Wsh)[i] = ((const float4*)W)[i];
    __syncthreads();

    const int warp = tid >> 5, lane = tid & 31;
    constexpr int V = NC / 32;                // 4 or 2 columns per lane

    for (int row = blockIdx.x * 8 + warp; row < M; row += gridDim.x * 8) {
        const float4* Ar = (const float4*)(A + (size_t)row * K);
        for (int i = lane; i < K / 4; i += 32) {
            float4 v = Ar[i];
            if (RELU_IN) {
                v.x = fmaxf(v.x, 0.f); v.y = fmaxf(v.y, 0.f);
                v.z = fmaxf(v.z, 0.f); v.w = fmaxf(v.w, 0.f);
            }
            ((float4*)xs[warp])[i] = v;
        }
        __syncwarp();

        float acc[V];
#pragma unroll
        for (int v = 0; v < V; v++) acc[v] = 0.f;

#pragma unroll 16
        for (int k = 0; k < K; k++) {
            float a = xs[warp][k];
#pragma unroll
            for (int v = 0; v < V; v++)
                acc[v] = fmaf(a, Wsh[k * NC + lane * V + v], acc[v]);
        }

        float* Cr = C + (size_t)row * NC + lane * V;
#pragma unroll
        for (int v = 0; v < V; v++) {
            float val = acc[v];
            if (BIAS) val += bias[lane * V + v];
            Cr[v] = val;
        }
        __syncwarp();
    }
}

// ------------- agg init: agg[i][f] = h[i][f] * dinv[i]^2 + bias[f] --------------
template<int F>
__global__ void init_agg(const float* __restrict__ h, const float* __restrict__ bias,
                         float* __restrict__ agg, int M) {
    int i = blockIdx.x * blockDim.x + threadIdx.x;       // over M * F/4 float4s
    int total = M * (F / 4);
    if (i < total) {
        int row = i / (F / 4);
        int c   = i - row * (F / 4);
        float dv = g_dinv[row];
        float d2 = dv * dv;
        float4 hv = ((const float4*)h)[i];
        float4 bv = ((const float4*)bias)[c];
        float4 o;
        o.x = fmaf(hv.x, d2, bv.x);
        o.y = fmaf(hv.y, d2, bv.y);
        o.z = fmaf(hv.z, d2, bv.z);
        o.w = fmaf(hv.w, d2, bv.w);
        ((float4*)agg)[i] = o;
    }
}

// ------------- edge scatter: agg[dst] += h[src] * dinv[src]*dinv[dst] -----------
// One warp per edge; lane handles F/32 features (float4/float2 gather + RED adds).
template<int F>
__global__ void edge_agg(const void* __restrict__ ei, const float* __restrict__ h,
                         float* __restrict__ agg, int E) {
    const int is64 = g_is64;
    long long w = ((long long)blockIdx.x * blockDim.x + threadIdx.x) >> 5;
    int lane = threadIdx.x & 31;
    if (w >= E) return;

    long long s, d;
    if (is64) {
        s = ((const long long*)ei)[w];
        d = ((const long long*)ei)[(size_t)E + w];
    } else {
        s = ((const int*)ei)[w];
        d = ((const int*)ei)[(size_t)E + w];
    }
    float coef = g_dinv[s] * g_dinv[d];

    constexpr int V = F / 32;
    const float* hp = h   + (size_t)s * F + lane * V;
    float*       ap = agg + (size_t)d * F + lane * V;
    if (V == 4) {
        float4 v = *(const float4*)hp;
        atomicAdd(ap + 0, v.x * coef);
        atomicAdd(ap + 1, v.y * coef);
        atomicAdd(ap + 2, v.z * coef);
        atomicAdd(ap + 3, v.w * coef);
    } else {
        float2 v = *(const float2*)hp;
        atomicAdd(ap + 0, v.x * coef);
        atomicAdd(ap + 1, v.y * coef);
    }
}

// --------------------------------- launch ---------------------------------------
extern "C" void kernel_launch(void* const* d_in, const int* in_sizes, int n_in,
                              void* d_out, int out_size) {
    const float* x  = (const float*)d_in[0];
    const void*  ei = d_in[1];
    const float* W1 = (const float*)d_in[2];
    const float* b1 = (const float*)d_in[3];
    const float* W2 = (const float*)d_in[4];
    const float* b2 = (const float*)d_in[5];
    const float* Wd = (const float*)d_in[6];
    const float* bd = (const float*)d_in[7];

    const int N = in_sizes[0] / IN_F;     // 100000
    const int E = in_sizes[1] / 2;        // 1.6M (element count, dtype-independent)

    float* out = (float*)d_out;           // x_recon [N, IN_F]
    float* z   = out + (size_t)N * IN_F;  // z       [N, OUT_F]

    float *h0p, *agg1p, *h2p;
    cudaGetSymbolAddress((void**)&h0p,  g_h0);
    cudaGetSymbolAddress((void**)&agg1p, g_agg1);
    cudaGetSymbolAddress((void**)&h2p,  g_h2);

    // 64KB dynamic SMEM for the 128x128 weight tile
    cudaFuncSetAttribute(gemm_kernel<IN_F, HID_F, false, false>,
                         cudaFuncAttributeMaxDynamicSharedMemorySize, IN_F * HID_F * 4);

    const int T = 256;
    detect_idx_dtype<<<1, 64>>>((const unsigned int*)ei);
    zero_deg<<<(N + T - 1) / T, T>>>(N);
    deg_kernel<<<(E + T - 1) / T, T>>>(ei, E);
    dinv_kernel<<<(N + T - 1) / T, T>>>(N);

    // layer 1: h0 = x @ W1 ; agg1 = scatter + self-loop + b1 (relu deferred to GEMM2 read)
    gemm_kernel<IN_F, HID_F, false, false><<<444, T, IN_F * HID_F * 4>>>(x, W1, nullptr, h0p, N);
    init_agg<HID_F><<<(N * (HID_F / 4) + T - 1) / T, T>>>(h0p, b1, agg1p, N);
    {
        long long warps = (long long)E;
        int grid = (int)((warps * 32 + T - 1) / T);
        edge_agg<HID_F><<<grid, T>>>(ei, h0p, agg1p, E);
    }

    // layer 2: h2 = relu(agg1) @ W2 ; z = scatter + self-loop + b2 (written to output)
    gemm_kernel<HID_F, OUT_F, true, false><<<444, T, HID_F * OUT_F * 4>>>(agg1p, W2, nullptr, h2p, N);
    init_agg<OUT_F><<<(N * (OUT_F / 4) + T - 1) / T, T>>>(h2p, b2, z, N);
    {
        long long warps = (long long)E;
        int grid = (int)((warps * 32 + T - 1) / T);
        edge_agg<OUT_F><<<grid, T>>>(ei, h2p, z, E);
    }

    // decoder: x_recon = z @ Wd + bd
    gemm_kernel<OUT_F, IN_F, false, true><<<444, T, OUT_F * IN_F * 4>>>(z, Wd, bd, out, N);
}

// round 3
// speedup vs baseline: 1.7594x; 1.7594x over previous
#include <cuda_runtime.h>

#define IN_F   128
#define HID_F  128
#define OUT_F  64
#define MAX_N  100000
#define MAX_E  1600000

// ---------------- scratch (static device memory; no allocations) ----------------
__device__ float g_dinv  [MAX_N];
__device__ int   g_cnt   [MAX_N];
__device__ int   g_rowptr[MAX_N + 1];
__device__ int   g_pos   [MAX_N];
__device__ int   g_col   [MAX_E];
__device__ int   g_bsum  [512];
__device__ int   g_boff  [512];
__device__ float g_h0    [(size_t)MAX_N * HID_F];   // x @ W1
__device__ float g_agg1  [(size_t)MAX_N * HID_F];   // layer-1 aggregation (pre-relu)
__device__ float g_h2    [(size_t)MAX_N * OUT_F];   // relu(agg1) @ W2
__device__ int   g_is64;

// ---------------- edge-index dtype detection (int32 vs int64) -------------------
__global__ void detect_idx_dtype(const unsigned int* __restrict__ w) {
    if (threadIdx.x == 0 && blockIdx.x == 0) {
        int is64 = 1;
        for (int i = 1; i < 64; i += 2)
            if (w[i] != 0u) is64 = 0;
        g_is64 = is64;
    }
}

__device__ __forceinline__ void load_edge(const void* ei, int E, int i, int is64,
                                          int& s, int& d) {
    if (is64) {
        s = (int)((const long long*)ei)[i];
        d = (int)((const long long*)ei)[(size_t)E + i];
    } else {
        s = ((const int*)ei)[i];
        d = ((const int*)ei)[(size_t)E + i];
    }
}

// ---------------- CSR build -----------------------------------------------------
__global__ void zero_cnt(int n) {
    int i = blockIdx.x * blockDim.x + threadIdx.x;
    if (i < n) g_cnt[i] = 0;
}

__global__ void count_kernel(const void* __restrict__ ei, int E) {
    const int is64 = g_is64;
    int i = blockIdx.x * blockDim.x + threadIdx.x;
    if (i < E) {
        int s, d; load_edge(ei, E, i, is64, s, d);
        atomicAdd(&g_cnt[d], 1);
    }
}

// per-block exclusive scan of g_cnt (256/block); writes partials into g_rowptr,
// block totals into g_bsum
__global__ void scan_block(int n) {
    __shared__ int sh[256];
    int tid = threadIdx.x;
    int i = blockIdx.x * 256 + tid;
    int v = (i < n) ? g_cnt[i] : 0;
    sh[tid] = v;
    __syncthreads();
#pragma unroll
    for (int off = 1; off < 256; off <<= 1) {
        int t = (tid >= off) ? sh[tid - off] : 0;
        __syncthreads();
        sh[tid] += t;
        __syncthreads();
    }
    if (i < n) g_rowptr[i] = sh[tid] - v;       // exclusive within block
    if (tid == 255) g_bsum[blockIdx.x] = sh[255];
}

// single-block exclusive scan of block sums
__global__ void scan_top(int nblocks) {
    __shared__ int sh[512];
    int tid = threadIdx.x;
    int v = (tid < nblocks) ? g_bsum[tid] : 0;
    sh[tid] = v;
    __syncthreads();
#pragma unroll
    for (int off = 1; off < 512; off <<= 1) {
        int t = (tid >= off) ? sh[tid - off] : 0;
        __syncthreads();
        sh[tid] += t;
        __syncthreads();
    }
    if (tid < nblocks) g_boff[tid] = sh[tid] - v;
}

// add block offsets; init pos; compute dinv; set rowptr[n]
__global__ void scan_add(int n, int E) {
    int i = blockIdx.x * blockDim.x + threadIdx.x;
    if (i < n) {
        int r = g_rowptr[i] + g_boff[blockIdx.x * blockDim.x / 256 + (threadIdx.x >> 8)];
        // blockDim must be 256 so the offset index is just blockIdx.x:
        r = g_rowptr[i] + g_boff[blockIdx.x];
        g_rowptr[i] = r;
        g_pos[i] = r;
        g_dinv[i] = rsqrtf((float)g_cnt[i] + 1.0f);
    }
    if (i == 0) g_rowptr[n] = E;
}

__global__ void fill_kernel(const void* __restrict__ ei, int E) {
    const int is64 = g_is64;
    int i = blockIdx.x * blockDim.x + threadIdx.x;
    if (i < E) {
        int s, d; load_edge(ei, E, i, is64, s, d);
        int idx = atomicAdd(&g_pos[d], 1);
        g_col[idx] = s;
    }
}

// ---------------- GEMM: C[M,NC] = op(A)[M,K] @ W[K,NC] (+bias) -------------------
// W whole in SMEM. 8 warps/block, R=4 rows per warp, k unrolled by 4.
// Per 4 k-steps/lane: R LDG.128 (A broadcast) + 4 LDS.128/64 (W) + 4*R*V FFMA.
template<int K, int NC, bool RELU_IN, bool BIAS>
__global__ void __launch_bounds__(256) gemm_kernel(
        const float* __restrict__ A, const float* __restrict__ W,
        const float* __restrict__ bias, float* __restrict__ C, int M) {
    extern __shared__ float Wsh[];            // K*NC floats
    const int tid = threadIdx.x;
    for (int i = tid; i < K * NC / 4; i += 256)
        ((float4*)Wsh)[i] = ((const float4*)W)[i];
    __syncthreads();

    const int warp = tid >> 5, lane = tid & 31;
    constexpr int V = NC / 32;                // 4 or 2 cols per lane
    constexpr int R = 4;                      // rows per warp

    int row0 = (blockIdx.x * 8 + warp) * R;
    if (row0 >= M) return;

    float acc[R][V];
#pragma unroll
    for (int r = 0; r < R; r++)
#pragma unroll
        for (int v = 0; v < V; v++) acc[r][v] = 0.f;

    const float4* A4 = (const float4*)(A + (size_t)row0 * K);
    constexpr int K4 = K / 4;

#pragma unroll 4
    for (int k4 = 0; k4 < K4; k4++) {
        float4 a[R];
#pragma unroll
        for (int r = 0; r < R; r++) {
            float4 av = A4[r * K4 + k4];
            if (RELU_IN) {
                av.x = fmaxf(av.x, 0.f); av.y = fmaxf(av.y, 0.f);
                av.z = fmaxf(av.z, 0.f); av.w = fmaxf(av.w, 0.f);
            }
            a[r] = av;
        }
#pragma unroll
        for (int kk = 0; kk < 4; kk++) {
            const float* wrow = Wsh + (k4 * 4 + kk) * NC;
            float w[V];
            if (V == 4) {
                float4 wv = ((const float4*)wrow)[lane];
                w[0] = wv.x; w[1] = wv.y; w[2] = wv.z; w[3] = wv.w;
            } else {
                float2 wv = ((const float2*)wrow)[lane];
                w[0] = wv.x; w[1] = wv.y;
            }
#pragma unroll
            for (int r = 0; r < R; r++) {
                float av = ((const float*)&a[r])[kk];
#pragma unroll
                for (int v = 0; v < V; v++)
                    acc[r][v] = fmaf(av, w[v], acc[r][v]);
            }
        }
    }

#pragma unroll
    for (int r = 0; r < R; r++) {
        if (row0 + r >= M) break;
        float* Cr = C + (size_t)(row0 + r) * NC + lane * V;
        if (V == 4) {
            float4 o;
            o.x = acc[r][0]; o.y = acc[r][1]; o.z = acc[r][2]; o.w = acc[r][3];
            if (BIAS) {
                float4 bv = ((const float4*)bias)[lane];
                o.x += bv.x; o.y += bv.y; o.z += bv.z; o.w += bv.w;
            }
            *(float4*)Cr = o;
        } else {
            float2 o;
            o.x = acc[r][0]; o.y = acc[r][1];
            if (BIAS) {
                float2 bv = ((const float2*)bias)[lane];
                o.x += bv.x; o.y += bv.y;
            }
            *(float2*)Cr = o;
        }
    }
}

// ------------- CSR gather aggregation: out[i] = sum_{s in N(i)} h[s]*dinv[s]*dinv[i]
//               + h[i]*dinv[i]^2 + bias  (one warp per destination row) ----------
template<int F>
__global__ void __launch_bounds__(256) gather_agg(
        const float* __restrict__ h, const float* __restrict__ bias,
        float* __restrict__ out, int Nn) {
    int w = (blockIdx.x * 256 + threadIdx.x) >> 5;
    int lane = threadIdx.x & 31;
    if (w >= Nn) return;
    constexpr int V = F / 32;

    float dv = g_dinv[w];
    float acc[V];

    // self-loop + bias
    if (V == 4) {
        float4 hv = ((const float4*)(h + (size_t)w * F))[lane];
        float4 bv = ((const float4*)bias)[lane];
        float d2 = dv * dv;
        acc[0] = fmaf(hv.x, d2, bv.x); acc[1] = fmaf(hv.y, d2, bv.y);
        acc[2] = fmaf(hv.z, d2, bv.z); acc[3] = fmaf(hv.w, d2, bv.w);
    } else {
        float2 hv = ((const float2*)(h + (size_t)w * F))[lane];
        float2 bv = ((const float2*)bias)[lane];
        float d2 = dv * dv;
        acc[0] = fmaf(hv.x, d2, bv.x); acc[1] = fmaf(hv.y, d2, bv.y);
    }

    int beg = g_rowptr[w], end = g_rowptr[w + 1];
#pragma unroll 2
    for (int j = beg; j < end; j++) {
        int s = g_col[j];                       // warp-uniform broadcast load
        float coef = g_dinv[s] * dv;
        if (V == 4) {
            float4 v = ((const float4*)(h + (size_t)s * F))[lane];
            acc[0] = fmaf(v.x, coef, acc[0]); acc[1] = fmaf(v.y, coef, acc[1]);
            acc[2] = fmaf(v.z, coef, acc[2]); acc[3] = fmaf(v.w, coef, acc[3]);
        } else {
            float2 v = ((const float2*)(h + (size_t)s * F))[lane];
            acc[0] = fmaf(v.x, coef, acc[0]); acc[1] = fmaf(v.y, coef, acc[1]);
        }
    }

    float* op = out + (size_t)w * F + lane * V;
    if (V == 4) { float4 o = {acc[0], acc[1], acc[2], acc[3]}; *(float4*)op = o; }
    else        { float2 o = {acc[0], acc[1]};                 *(float2*)op = o; }
}

// --------------------------------- launch ---------------------------------------
extern "C" void kernel_launch(void* const* d_in, const int* in_sizes, int n_in,
                              void* d_out, int out_size) {
    const float* x  = (const float*)d_in[0];
    const void*  ei = d_in[1];
    const float* W1 = (const float*)d_in[2];
    const float* b1 = (const float*)d_in[3];
    const float* W2 = (const float*)d_in[4];
    const float* b2 = (const float*)d_in[5];
    const float* Wd = (const float*)d_in[6];
    const float* bd = (const float*)d_in[7];

    const int N = in_sizes[0] / IN_F;     // 100000
    const int E = in_sizes[1] / 2;        // 1.6M

    float* out = (float*)d_out;           // x_recon [N, IN_F]
    float* z   = out + (size_t)N * IN_F;  // z       [N, OUT_F]

    float *h0p, *agg1p, *h2p;
    cudaGetSymbolAddress((void**)&h0p,  g_h0);
    cudaGetSymbolAddress((void**)&agg1p, g_agg1);
    cudaGetSymbolAddress((void**)&h2p,  g_h2);

    cudaFuncSetAttribute(gemm_kernel<IN_F, HID_F, false, false>,
                         cudaFuncAttributeMaxDynamicSharedMemorySize, IN_F * HID_F * 4);

    const int T = 256;
    const int nScanBlocks = (N + 255) / 256;

    // CSR build (also yields dinv)
    detect_idx_dtype<<<1, 64>>>((const unsigned int*)ei);
    zero_cnt<<<(N + T - 1) / T, T>>>(N);
    count_kernel<<<(E + T - 1) / T, T>>>(ei, E);
    scan_block<<<nScanBlocks, 256>>>(N);
    scan_top<<<1, 512>>>(nScanBlocks);
    scan_add<<<nScanBlocks, 256>>>(N, E);
    fill_kernel<<<(E + T - 1) / T, T>>>(ei, E);

    const int gemmGrid = (N + 31) / 32;
    const int aggGrid  = (N * 32 + T - 1) / T;   // warp per node

    // layer 1
    gemm_kernel<IN_F, HID_F, false, false><<<gemmGrid, T, IN_F * HID_F * 4>>>(x, W1, nullptr, h0p, N);
    gather_agg<HID_F><<<aggGrid, T>>>(h0p, b1, agg1p, N);

    // layer 2 (relu fused into GEMM read); z written straight into d_out
    gemm_kernel<HID_F, OUT_F, true, false><<<gemmGrid, T, HID_F * OUT_F * 4>>>(agg1p, W2, nullptr, h2p, N);
    gather_agg<OUT_F><<<aggGrid, T>>>(h2p, b2, z, N);

    // decoder
    gemm_kernel<OUT_F, IN_F, false, true><<<gemmGrid, T, OUT_F * IN_F * 4>>>(z, Wd, bd, out, N);
}

// round 4
// speedup vs baseline: 4.0665x; 2.3113x over previous
#include <cuda_runtime.h>
#include <cstdint>

#define IN_F   128
#define HID_F  128
#define OUT_F  64
#define MAX_N  100000
#define MAX_E  1600000

// ---------------- scratch (static device memory; no allocations) ----------------
__device__ float g_dinv  [MAX_N];
__device__ int   g_cnt   [MAX_N];
__device__ int   g_rowptr[MAX_N + 1];
__device__ int   g_pos   [MAX_N];
__device__ int2  g_ecol  [MAX_E];          // .x = src id, .y = coef (float bits)
__device__ int   g_bsum  [512];
__device__ int   g_boff  [512];
__device__ float g_h0    [(size_t)MAX_N * HID_F];
__device__ float g_agg1  [(size_t)MAX_N * HID_F];
__device__ float g_h2    [(size_t)MAX_N * OUT_F];
__device__ int   g_is64;

// ---------------- edge-index dtype detection (int32 vs int64) -------------------
__global__ void detect_idx_dtype(const unsigned int* __restrict__ w) {
    if (threadIdx.x == 0 && blockIdx.x == 0) {
        int is64 = 1;
        for (int i = 1; i < 64; i += 2)
            if (w[i] != 0u) is64 = 0;
        g_is64 = is64;
    }
}

__device__ __forceinline__ void load_edge(const void* ei, int E, int i, int is64,
                                          int& s, int& d) {
    if (is64) {
        s = (int)((const long long*)ei)[i];
        d = (int)((const long long*)ei)[(size_t)E + i];
    } else {
        s = ((const int*)ei)[i];
        d = ((const int*)ei)[(size_t)E + i];
    }
}

// ---------------- CSR build -----------------------------------------------------
__global__ void zero_cnt(int n) {
    int i = blockIdx.x * blockDim.x + threadIdx.x;
    if (i < n) g_cnt[i] = 0;
}

__global__ void count_kernel(const void* __restrict__ ei, int E) {
    const int is64 = g_is64;
    int i = blockIdx.x * blockDim.x + threadIdx.x;
    if (i < E) {
        int s, d; load_edge(ei, E, i, is64, s, d);
        atomicAdd(&g_cnt[d], 1);
    }
}

__global__ void scan_block(int n) {
    __shared__ int sh[256];
    int tid = threadIdx.x;
    int i = blockIdx.x * 256 + tid;
    int v = (i < n) ? g_cnt[i] : 0;
    sh[tid] = v;
    __syncthreads();
#pragma unroll
    for (int off = 1; off < 256; off <<= 1) {
        int t = (tid >= off) ? sh[tid - off] : 0;
        __syncthreads();
        sh[tid] += t;
        __syncthreads();
    }
    if (i < n) g_rowptr[i] = sh[tid] - v;
    if (tid == 255) g_bsum[blockIdx.x] = sh[255];
}

__global__ void scan_top(int nblocks) {
    __shared__ int sh[512];
    int tid = threadIdx.x;
    int v = (tid < nblocks) ? g_bsum[tid] : 0;
    sh[tid] = v;
    __syncthreads();
#pragma unroll
    for (int off = 1; off < 512; off <<= 1) {
        int t = (tid >= off) ? sh[tid - off] : 0;
        __syncthreads();
        sh[tid] += t;
        __syncthreads();
    }
    if (tid < nblocks) g_boff[tid] = sh[tid] - v;
}

__global__ void scan_add(int n, int E) {
    int i = blockIdx.x * 256 + threadIdx.x;
    if (i < n) {
        int r = g_rowptr[i] + g_boff[blockIdx.x];
        g_rowptr[i] = r;
        g_pos[i] = r;
        g_dinv[i] = rsqrtf((float)g_cnt[i] + 1.0f);
    }
    if (i == 0) g_rowptr[n] = E;
}

__global__ void fill_kernel(const void* __restrict__ ei, int E) {
    const int is64 = g_is64;
    int i = blockIdx.x * blockDim.x + threadIdx.x;
    if (i < E) {
        int s, d; load_edge(ei, E, i, is64, s, d);
        int idx = atomicAdd(&g_pos[d], 1);
        float coef = g_dinv[s] * g_dinv[d];
        g_ecol[idx] = make_int2(s, __float_as_int(coef));
    }
}

// ---------------- TF32 tensor-core GEMM ------------------------------------------
// C[M,NC] = op(A)[M,K] @ W[K,NC] (+bias), fp32 accumulate.
// Persistent blocks; W (tf32-rounded) staged once in padded smem; 32-row A tiles.
// 8 warps = 2 m-groups x 4 n-groups; mma.sync.m16n8k8.tf32.
__device__ __forceinline__ unsigned f2tf32(float f) {
    unsigned u;
    asm("cvt.rna.tf32.f32 %0, %1;" : "=r"(u) : "f"(f));
    return u;
}

template<int K, int NC, bool RELU_IN, bool BIAS>
__global__ void __launch_bounds__(256) gemm_tc(
        const float* __restrict__ A, const float* __restrict__ W,
        const float* __restrict__ bias, float* __restrict__ C, int M) {
    constexpr int KP   = K + 4;       // A smem row stride (conflict-free frags)
    constexpr int NCP  = NC + 8;      // W smem row stride (conflict-free frags)
    constexpr int NT_W = NC / 32;     // 8-wide n-tiles per warp (4 or 2)

    extern __shared__ unsigned sh[];
    unsigned* Ws = sh;                // K * NCP
    unsigned* As = sh + K * NCP;      // 32 * KP

    const int tid = threadIdx.x;
    // stage W once (tf32-rounded); first in-loop __syncthreads covers visibility
    for (int i = tid; i < K * NC; i += 256) {
        int k = i / NC, n = i - k * NC;
        Ws[k * NCP + n] = f2tf32(W[i]);
    }

    const int warp = tid >> 5, lane = tid & 31;
    const int g = lane >> 2, tg = lane & 3;
    const int mi = warp >> 2;         // 0..1  (16-row half)
    const int ni = warp & 3;          // 0..3  (n quarter)
    const int ntiles = (M + 31) >> 5;

    for (int tile = blockIdx.x; tile < ntiles; tile += gridDim.x) {
        const int row0 = tile << 5;
        __syncthreads();              // prior iteration's As reads complete
        for (int i = tid; i < 32 * K; i += 256) {
            int r = i / K, k = i - r * K;
            float v = 0.f;
            if (row0 + r < M) v = A[(size_t)(row0 + r) * K + k];
            if (RELU_IN) v = fmaxf(v, 0.f);
            As[r * KP + k] = f2tf32(v);
        }
        __syncthreads();

        float acc[NT_W][4];
#pragma unroll
        for (int t = 0; t < NT_W; t++)
#pragma unroll
            for (int v = 0; v < 4; v++) acc[t][v] = 0.f;

        const unsigned* Arow = As + (mi * 16 + g) * KP;
#pragma unroll
        for (int k0 = 0; k0 < K; k0 += 8) {
            unsigned a0 = Arow[k0 + tg];
            unsigned a1 = Arow[8 * KP + k0 + tg];
            unsigned a2 = Arow[k0 + tg + 4];
            unsigned a3 = Arow[8 * KP + k0 + tg + 4];
#pragma unroll
            for (int t = 0; t < NT_W; t++) {
                int n0 = ni * (NT_W * 8) + t * 8;
                unsigned b0 = Ws[(k0 + tg) * NCP + n0 + g];
                unsigned b1 = Ws[(k0 + tg + 4) * NCP + n0 + g];
                asm volatile(
                    "mma.sync.aligned.m16n8k8.row.col.f32.tf32.tf32.f32 "
                    "{%0,%1,%2,%3},{%4,%5,%6,%7},{%8,%9},{%0,%1,%2,%3};\n"
                    : "+f"(acc[t][0]), "+f"(acc[t][1]),
                      "+f"(acc[t][2]), "+f"(acc[t][3])
                    : "r"(a0), "r"(a1), "r"(a2), "r"(a3), "r"(b0), "r"(b1));
            }
        }

        const int r0 = row0 + mi * 16 + g;
        const int r1 = r0 + 8;
#pragma unroll
        for (int t = 0; t < NT_W; t++) {
            int n0 = ni * (NT_W * 8) + t * 8 + 2 * tg;
            float bx = 0.f, by = 0.f;
            if (BIAS) { bx = bias[n0]; by = bias[n0 + 1]; }
            if (r0 < M) {
                float2 o = {acc[t][0] + bx, acc[t][1] + by};
                *(float2*)(C + (size_t)r0 * NC + n0) = o;
            }
            if (r1 < M) {
                float2 o = {acc[t][2] + bx, acc[t][3] + by};
                *(float2*)(C + (size_t)r1 * NC + n0) = o;
            }
        }
    }
}

// ------------- CSR gather aggregation (warp per destination row) ----------------
template<int F>
__global__ void __launch_bounds__(256) gather_agg(
        const float* __restrict__ h, const float* __restrict__ bias,
        float* __restrict__ out, int Nn) {
    int w = (blockIdx.x * 256 + threadIdx.x) >> 5;
    int lane = threadIdx.x & 31;
    if (w >= Nn) return;
    constexpr int V = F / 32;

    float dv = g_dinv[w];
    float acc[V];

    if (V == 4) {
        float4 hv = ((const float4*)(h + (size_t)w * F))[lane];
        float4 bv = ((const float4*)bias)[lane];
        float d2 = dv * dv;
        acc[0] = fmaf(hv.x, d2, bv.x); acc[1] = fmaf(hv.y, d2, bv.y);
        acc[2] = fmaf(hv.z, d2, bv.z); acc[3] = fmaf(hv.w, d2, bv.w);
    } else {
        float2 hv = ((const float2*)(h + (size_t)w * F))[lane];
        float2 bv = ((const float2*)bias)[lane];
        float d2 = dv * dv;
        acc[0] = fmaf(hv.x, d2, bv.x); acc[1] = fmaf(hv.y, d2, bv.y);
    }

    int beg = g_rowptr[w], end = g_rowptr[w + 1];
#pragma unroll 4
    for (int j = beg; j < end; j++) {
        int2 e = g_ecol[j];                     // warp-uniform broadcast load
        int s = e.x;
        float coef = __int_as_float(e.y);
        if (V == 4) {
            float4 v = ((const float4*)(h + (size_t)s * F))[lane];
            acc[0] = fmaf(v.x, coef, acc[0]); acc[1] = fmaf(v.y, coef, acc[1]);
            acc[2] = fmaf(v.z, coef, acc[2]); acc[3] = fmaf(v.w, coef, acc[3]);
        } else {
            float2 v = ((const float2*)(h + (size_t)s * F))[lane];
            acc[0] = fmaf(v.x, coef, acc[0]); acc[1] = fmaf(v.y, coef, acc[1]);
        }
    }

    float* op = out + (size_t)w * F + lane * V;
    if (V == 4) { float4 o = {acc[0], acc[1], acc[2], acc[3]}; *(float4*)op = o; }
    else        { float2 o = {acc[0], acc[1]};                 *(float2*)op = o; }
}

// --------------------------------- launch ---------------------------------------
extern "C" void kernel_launch(void* const* d_in, const int* in_sizes, int n_in,
                              void* d_out, int out_size) {
    const float* x  = (const float*)d_in[0];
    const void*  ei = d_in[1];
    const float* W1 = (const float*)d_in[2];
    const float* b1 = (const float*)d_in[3];
    const float* W2 = (const float*)d_in[4];
    const float* b2 = (const float*)d_in[5];
    const float* Wd = (const float*)d_in[6];
    const float* bd = (const float*)d_in[7];

    const int N = in_sizes[0] / IN_F;     // 100000
    const int E = in_sizes[1] / 2;        // 1.6M

    float* out = (float*)d_out;           // x_recon [N, IN_F]
    float* z   = out + (size_t)N * IN_F;  // z       [N, OUT_F]

    float *h0p, *agg1p, *h2p;
    cudaGetSymbolAddress((void**)&h0p,   g_h0);
    cudaGetSymbolAddress((void**)&agg1p, g_agg1);
    cudaGetSymbolAddress((void**)&h2p,   g_h2);

    // smem: W tile (K*(NC+8)) + A tile (32*(K+4)), in 4-byte words
    const int smem1 = (IN_F  * (HID_F + 8) + 32 * (IN_F  + 4)) * 4;  // 86528
    const int smem2 = (HID_F * (OUT_F + 8) + 32 * (HID_F + 4)) * 4;  // 53760
    const int smem3 = (OUT_F * (IN_F  + 8) + 32 * (OUT_F + 4)) * 4;  // 43520
    cudaFuncSetAttribute(gemm_tc<IN_F, HID_F, false, false>,
                         cudaFuncAttributeMaxDynamicSharedMemorySize, smem1);
    cudaFuncSetAttribute(gemm_tc<HID_F, OUT_F, true, false>,
                         cudaFuncAttributeMaxDynamicSharedMemorySize, smem2);
    cudaFuncSetAttribute(gemm_tc<OUT_F, IN_F, false, true>,
                         cudaFuncAttributeMaxDynamicSharedMemorySize, smem3);

    const int T = 256;
    const int nScanBlocks = (N + 255) / 256;

    // CSR build (also yields dinv + per-edge coef)
    detect_idx_dtype<<<1, 64>>>((const unsigned int*)ei);
    zero_cnt<<<(N + T - 1) / T, T>>>(N);
    count_kernel<<<(E + T - 1) / T, T>>>(ei, E);
    scan_block<<<nScanBlocks, 256>>>(N);
    scan_top<<<1, 512>>>(nScanBlocks);
    scan_add<<<nScanBlocks, 256>>>(N, E);
    fill_kernel<<<(E + T - 1) / T, T>>>(ei, E);

    const int aggGrid = (N * 32 + T - 1) / T;     // warp per node

    // layer 1
    gemm_tc<IN_F, HID_F, false, false><<<296, T, smem1>>>(x, W1, nullptr, h0p, N);
    gather_agg<HID_F><<<aggGrid, T>>>(h0p, b1, agg1p, N);

    // layer 2 (relu fused into GEMM A-stage); z written straight into d_out
    gemm_tc<HID_F, OUT_F, true, false><<<592, T, smem2>>>(agg1p, W2, nullptr, h2p, N);
    gather_agg<OUT_F><<<aggGrid, T>>>(h2p, b2, z, N);

    // decoder
    gemm_tc<OUT_F, IN_F, false, true><<<592, T, smem3>>>(z, Wd, bd, out, N);
}

// round 5
// speedup vs baseline: 4.6400x; 1.1410x over previous
#include <cuda_runtime.h>
#include <cstdint>

#define IN_F   128
#define HID_F  128
#define OUT_F  64
#define MAX_N  100000
#define MAX_E  1600000

// ---------------- scratch (static device memory; no allocations) ----------------
__device__ float g_dinv  [MAX_N];
__device__ int   g_cnt   [MAX_N];
__device__ int   g_rowptr[MAX_N + 1];
__device__ int   g_pos   [MAX_N];
__device__ int2  g_ecol  [MAX_E];          // .x = src id, .y = coef (float bits)
__device__ int   g_bsum  [512];
__device__ int   g_boff  [512];
__device__ float g_h0    [(size_t)MAX_N * HID_F];
__device__ float g_agg1  [(size_t)MAX_N * HID_F];
__device__ float g_h2    [(size_t)MAX_N * OUT_F];
__device__ int   g_is64;

// ---------------- zero counts + edge-index dtype detection ----------------------
__global__ void init_zero_detect(const unsigned int* __restrict__ w, int n) {
    int i = blockIdx.x * blockDim.x + threadIdx.x;
    if (i < n) g_cnt[i] = 0;
    if (i == 0) {
        int is64 = 1;
        for (int j = 1; j < 64; j += 2)
            if (w[j] != 0u) is64 = 0;
        g_is64 = is64;
    }
}

__device__ __forceinline__ void load_edge(const void* ei, int E, int i, int is64,
                                          int& s, int& d) {
    if (is64) {
        s = (int)((const long long*)ei)[i];
        d = (int)((const long long*)ei)[(size_t)E + i];
    } else {
        s = ((const int*)ei)[i];
        d = ((const int*)ei)[(size_t)E + i];
    }
}

// ---------------- CSR scan chain ------------------------------------------------
__global__ void scan_block(int n) {
    __shared__ int sh[256];
    int tid = threadIdx.x;
    int i = blockIdx.x * 256 + tid;
    int v = (i < n) ? g_cnt[i] : 0;
    sh[tid] = v;
    __syncthreads();
#pragma unroll
    for (int off = 1; off < 256; off <<= 1) {
        int t = (tid >= off) ? sh[tid - off] : 0;
        __syncthreads();
        sh[tid] += t;
        __syncthreads();
    }
    if (i < n) g_rowptr[i] = sh[tid] - v;
    if (tid == 255) g_bsum[blockIdx.x] = sh[255];
}

__global__ void scan_top(int nblocks) {
    __shared__ int sh[512];
    int tid = threadIdx.x;
    int v = (tid < nblocks) ? g_bsum[tid] : 0;
    sh[tid] = v;
    __syncthreads();
#pragma unroll
    for (int off = 1; off < 512; off <<= 1) {
        int t = (tid >= off) ? sh[tid - off] : 0;
        __syncthreads();
        sh[tid] += t;
        __syncthreads();
    }
    if (tid < nblocks) g_boff[tid] = sh[tid] - v;
}

__global__ void scan_add(int n, int E) {
    int i = blockIdx.x * 256 + threadIdx.x;
    if (i < n) {
        int r = g_rowptr[i] + g_boff[blockIdx.x];
        g_rowptr[i] = r;
        g_pos[i] = r;
        g_dinv[i] = rsqrtf((float)g_cnt[i] + 1.0f);
    }
    if (i == 0) g_rowptr[n] = E;
}

__global__ void fill_kernel(const void* __restrict__ ei, int E) {
    const int is64 = g_is64;
    int i = blockIdx.x * blockDim.x + threadIdx.x;
    if (i < E) {
        int s, d; load_edge(ei, E, i, is64, s, d);
        int idx = atomicAdd(&g_pos[d], 1);
        float coef = g_dinv[s] * g_dinv[d];
        g_ecol[idx] = make_int2(s, __float_as_int(coef));
    }
}

// ---------------- TF32 tensor-core GEMM ------------------------------------------
// C[M,NC] = op(A)[M,K] @ W[K,NC] (+bias), fp32 accumulate. 64-row tiles,
// 8 warps = 2 m-groups (32 rows, 2 m-subtiles each) x 4 n-groups; B-frags reused
// across m-subtiles. Vectorized (float4) staging of W (once) and A (per tile).
// COUNT: fused degree-count prologue (grid-stride REDs over edge dst).
__device__ __forceinline__ unsigned f2tf32(float f) {
    unsigned u;
    asm("cvt.rna.tf32.f32 %0, %1;" : "=r"(u) : "f"(f));
    return u;
}

template<int K, int NC, bool RELU_IN, bool BIAS, bool COUNT>
__global__ void __launch_bounds__(256) gemm_tc(
        const float* __restrict__ A, const float* __restrict__ W,
        const float* __restrict__ bias, float* __restrict__ C, int M,
        const void* __restrict__ ei, int E) {
    constexpr int KP   = K + 4;        // A smem row stride (words)
    constexpr int NCP  = NC + 8;       // W smem row stride (words)
    constexpr int NQ   = NC / 4;       // warp n-quarter width... (NC/4 cols per ni)
    constexpr int NT_W = NC / 32;      // 8-wide n-tiles per warp
    constexpr int K4   = K / 4;

    extern __shared__ unsigned sh[];
    unsigned* Ws = sh;                 // K * NCP
    unsigned* As = sh + K * NCP;       // 64 * KP

    const int tid = threadIdx.x;

    // ---- stage W once (tf32-rounded, vectorized) ----
    for (int i = tid; i < K * NC / 4; i += 256) {
        int k = i / (NC / 4), n4 = i - k * (NC / 4);
        float4 v = ((const float4*)W)[i];
        uint4 u = {f2tf32(v.x), f2tf32(v.y), f2tf32(v.z), f2tf32(v.w)};
        *(uint4*)(Ws + k * NCP + n4 * 4) = u;
    }

    // ---- fused degree count (independent of smem; hidden behind GEMM traffic) ----
    if (COUNT) {
        const int is64 = g_is64;
        for (int i = blockIdx.x * 256 + tid; i < E; i += gridDim.x * 256) {
            int d = is64 ? (int)((const long long*)ei)[(size_t)E + i]
                         : ((const int*)ei)[(size_t)E + i];
            atomicAdd(&g_cnt[d], 1);
        }
    }

    const int warp = tid >> 5, lane = tid & 31;
    const int g = lane >> 2, tg = lane & 3;
    const int mi = warp >> 2;          // 0..1  (32-row half)
    const int ni = warp & 3;           // 0..3  (n quarter)
    const int ntiles = (M + 63) >> 6;

    for (int tile = blockIdx.x; tile < ntiles; tile += gridDim.x) {
        const int row0 = tile << 6;
        __syncthreads();               // prior As reads done / W visible
        // ---- stage 64-row A tile (vectorized) ----
        for (int i = tid; i < 64 * K4; i += 256) {
            int r = i / K4, c4 = i - r * K4;
            float4 v = {0.f, 0.f, 0.f, 0.f};
            if (row0 + r < M) v = *(const float4*)(A + (size_t)(row0 + r) * K + c4 * 4);
            if (RELU_IN) {
                v.x = fmaxf(v.x, 0.f); v.y = fmaxf(v.y, 0.f);
                v.z = fmaxf(v.z, 0.f); v.w = fmaxf(v.w, 0.f);
            }
            uint4 u = {f2tf32(v.x), f2tf32(v.y), f2tf32(v.z), f2tf32(v.w)};
            *(uint4*)(As + r * KP + c4 * 4) = u;
        }
        __syncthreads();

        float acc[2][NT_W][4];
#pragma unroll
        for (int ms = 0; ms < 2; ms++)
#pragma unroll
            for (int t = 0; t < NT_W; t++)
#pragma unroll
                for (int v = 0; v < 4; v++) acc[ms][t][v] = 0.f;

        const unsigned* Arow0 = As + (mi * 32 + g) * KP;
        const unsigned* Arow1 = Arow0 + 16 * KP;
#pragma unroll
        for (int k0 = 0; k0 < K; k0 += 8) {
            unsigned a[2][4];
            a[0][0] = Arow0[k0 + tg];
            a[0][1] = Arow0[8 * KP + k0 + tg];
            a[0][2] = Arow0[k0 + tg + 4];
            a[0][3] = Arow0[8 * KP + k0 + tg + 4];
            a[1][0] = Arow1[k0 + tg];
            a[1][1] = Arow1[8 * KP + k0 + tg];
            a[1][2] = Arow1[k0 + tg + 4];
            a[1][3] = Arow1[8 * KP + k0 + tg + 4];
#pragma unroll
            for (int t = 0; t < NT_W; t++) {
                int n0 = ni * (NT_W * 8) + t * 8;
                unsigned b0 = Ws[(k0 + tg) * NCP + n0 + g];
                unsigned b1 = Ws[(k0 + tg + 4) * NCP + n0 + g];
#pragma unroll
                for (int ms = 0; ms < 2; ms++) {
                    asm volatile(
                        "mma.sync.aligned.m16n8k8.row.col.f32.tf32.tf32.f32 "
                        "{%0,%1,%2,%3},{%4,%5,%6,%7},{%8,%9},{%0,%1,%2,%3};\n"
                        : "+f"(acc[ms][t][0]), "+f"(acc[ms][t][1]),
                          "+f"(acc[ms][t][2]), "+f"(acc[ms][t][3])
                        : "r"(a[ms][0]), "r"(a[ms][1]), "r"(a[ms][2]), "r"(a[ms][3]),
                          "r"(b0), "r"(b1));
                }
            }
        }

#pragma unroll
        for (int ms = 0; ms < 2; ms++) {
            const int r0 = row0 + mi * 32 + ms * 16 + g;
            const int r1 = r0 + 8;
#pragma unroll
            for (int t = 0; t < NT_W; t++) {
                int n0 = ni * (NT_W * 8) + t * 8 + 2 * tg;
                float bx = 0.f, by = 0.f;
                if (BIAS) { bx = bias[n0]; by = bias[n0 + 1]; }
                if (r0 < M) {
                    float2 o = {acc[ms][t][0] + bx, acc[ms][t][1] + by};
                    *(float2*)(C + (size_t)r0 * NC + n0) = o;
                }
                if (r1 < M) {
                    float2 o = {acc[ms][t][2] + bx, acc[ms][t][3] + by};
                    *(float2*)(C + (size_t)r1 * NC + n0) = o;
                }
            }
        }
    }
    (void)NQ;
}

// ------------- CSR gather aggregation (warp per destination row) ----------------
template<int F>
__global__ void __launch_bounds__(256) gather_agg(
        const float* __restrict__ h, const float* __restrict__ bias,
        float* __restrict__ out, int Nn) {
    int w = (blockIdx.x * 256 + threadIdx.x) >> 5;
    int lane = threadIdx.x & 31;
    if (w >= Nn) return;
    constexpr int V = F / 32;

    float dv = g_dinv[w];
    float acc[V];

    if (V == 4) {
        float4 hv = ((const float4*)(h + (size_t)w * F))[lane];
        float4 bv = ((const float4*)bias)[lane];
        float d2 = dv * dv;
        acc[0] = fmaf(hv.x, d2, bv.x); acc[1] = fmaf(hv.y, d2, bv.y);
        acc[2] = fmaf(hv.z, d2, bv.z); acc[3] = fmaf(hv.w, d2, bv.w);
    } else {
        float2 hv = ((const float2*)(h + (size_t)w * F))[lane];
        float2 bv = ((const float2*)bias)[lane];
        float d2 = dv * dv;
        acc[0] = fmaf(hv.x, d2, bv.x); acc[1] = fmaf(hv.y, d2, bv.y);
    }

    int beg = g_rowptr[w], end = g_rowptr[w + 1];
#pragma unroll 4
    for (int j = beg; j < end; j++) {
        int2 e = g_ecol[j];                     // warp-uniform broadcast load
        int s = e.x;
        float coef = __int_as_float(e.y);
        if (V == 4) {
            float4 v = ((const float4*)(h + (size_t)s * F))[lane];
            acc[0] = fmaf(v.x, coef, acc[0]); acc[1] = fmaf(v.y, coef, acc[1]);
            acc[2] = fmaf(v.z, coef, acc[2]); acc[3] = fmaf(v.w, coef, acc[3]);
        } else {
            float2 v = ((const float2*)(h + (size_t)s * F))[lane];
            acc[0] = fmaf(v.x, coef, acc[0]); acc[1] = fmaf(v.y, coef, acc[1]);
        }
    }

    float* op = out + (size_t)w * F + lane * V;
    if (V == 4) { float4 o = {acc[0], acc[1], acc[2], acc[3]}; *(float4*)op = o; }
    else        { float2 o = {acc[0], acc[1]};                 *(float2*)op = o; }
}

// --------------------------------- launch ---------------------------------------
extern "C" void kernel_launch(void* const* d_in, const int* in_sizes, int n_in,
                              void* d_out, int out_size) {
    const float* x  = (const float*)d_in[0];
    const void*  ei = d_in[1];
    const float* W1 = (const float*)d_in[2];
    const float* b1 = (const float*)d_in[3];
    const float* W2 = (const float*)d_in[4];
    const float* b2 = (const float*)d_in[5];
    const float* Wd = (const float*)d_in[6];
    const float* bd = (const float*)d_in[7];

    const int N = in_sizes[0] / IN_F;     // 100000
    const int E = in_sizes[1] / 2;        // 1.6M

    float* out = (float*)d_out;           // x_recon [N, IN_F]
    float* z   = out + (size_t)N * IN_F;  // z       [N, OUT_F]

    float *h0p, *agg1p, *h2p;
    cudaGetSymbolAddress((void**)&h0p,   g_h0);
    cudaGetSymbolAddress((void**)&agg1p, g_agg1);
    cudaGetSymbolAddress((void**)&h2p,   g_h2);

    // smem (bytes): Ws K*(NC+8) + As 64*(K+4), 4B words
    const int smem1 = (IN_F  * (HID_F + 8) + 64 * (IN_F  + 4)) * 4;  // 103424
    const int smem2 = (HID_F * (OUT_F + 8) + 64 * (HID_F + 4)) * 4;  //  70656
    const int smem3 = (OUT_F * (IN_F  + 8) + 64 * (OUT_F + 4)) * 4;  //  52224
    cudaFuncSetAttribute(gemm_tc<IN_F, HID_F, false, false, true>,
                         cudaFuncAttributeMaxDynamicSharedMemorySize, smem1);
    cudaFuncSetAttribute(gemm_tc<HID_F, OUT_F, true, false, false>,
                         cudaFuncAttributeMaxDynamicSharedMemorySize, smem2);
    cudaFuncSetAttribute(gemm_tc<OUT_F, IN_F, false, true, false>,
                         cudaFuncAttributeMaxDynamicSharedMemorySize, smem3);

    const int T = 256;
    const int nScanBlocks = (N + 255) / 256;
    const int aggGrid = (N * 32 + T - 1) / T;     // warp per node

    // zero counts + dtype detect (one small kernel)
    init_zero_detect<<<nScanBlocks, 256>>>((const unsigned int*)ei, N);

    // layer-1 GEMM with fused degree count
    gemm_tc<IN_F, HID_F, false, false, true><<<296, T, smem1>>>(
        x, W1, nullptr, h0p, N, ei, E);

    // CSR scan + fill (also yields dinv + per-edge coef)
    scan_block<<<nScanBlocks, 256>>>(N);
    scan_top<<<1, 512>>>(nScanBlocks);
    scan_add<<<nScanBlocks, 256>>>(N, E);
    fill_kernel<<<(E + T - 1) / T, T>>>(ei, E);

    // layer-1 aggregation
    gather_agg<HID_F><<<aggGrid, T>>>(h0p, b1, agg1p, N);

    // layer 2 (relu fused into GEMM A-stage); z written straight into d_out
    gemm_tc<HID_F, OUT_F, true, false, false><<<444, T, smem2>>>(
        agg1p, W2, nullptr, h2p, N, nullptr, 0);
    gather_agg<OUT_F><<<aggGrid, T>>>(h2p, b2, z, N);

    // decoder
    gemm_tc<OUT_F, IN_F, false, true, false><<<592, T, smem3>>>(
        z, Wd, bd, out, N, nullptr, 0);
}